// round 6
// baseline (speedup 1.0000x reference)
#include <cuda_runtime.h>
#include <math.h>

// Problem constants
#define NPIX   65536        // B*H*W = 16*64*64
#define HW     4096         // 64*64
#define TILE   128          // pixels per block
#define NBLK   (NPIX/TILE)  // 512
#define NTHR   256
#define NSPLIT 8            // reduction splits (512 blocks -> 8 partials)

// Transposed table layout: sT[row*RS + g*GOFF + pix]
//   rows 0..15  = hi[i],  rows 16..47 = lo[j]
//   RS = 292: RS/4 = 73 == 1 (mod 8) -> bank-quad(row) = row mod 8
//   GOFF = 144 (mod 32 == 16 -> phase-1 STS conflict-free)
#define RS    292
#define GOFF  144
#define SRED_OFF (48 * RS)       // 14016
#define SMEM_FLOATS (SRED_OFF + 64)

// Output layout (flattened tuple, float32):
// zq[16,18,64,64] | loss | cb_entropy | indices[16,64,64] | group_indices[16,64,64,2] | avg_prob[2,512]
#define OFF_ZQ    0
#define OFF_LOSS  1179648
#define OFF_CBE   1179649
#define OFF_IDX   1179650
#define OFF_GIDX  1245186
#define OFF_AVGP  1376258

// Deterministic per-block partials (no float atomics -> bitwise reproducible)
__device__ float g_pavg[NBLK * 1024];
__device__ float g_red[NSPLIT * 1024];
__device__ float g_pcommit[NBLK];
__device__ float g_pent[NBLK];

__device__ __forceinline__ void fma2(unsigned long long& acc,
                                     unsigned long long a, unsigned long long b) {
    asm("fma.rn.f32x2 %0, %1, %2, %0;" : "+l"(acc) : "l"(a), "l"(b));
}
__device__ __forceinline__ float hsum2(unsigned long long acc) {
    float lo, hi;
    asm("mov.b64 {%0, %1}, %2;" : "=f"(lo), "=f"(hi) : "l"(acc));
    return lo + hi;
}

__global__ void __launch_bounds__(NTHR) bsq_main(const float* __restrict__ z,
                                                 float* __restrict__ out) {
    extern __shared__ float sT[];
    float* sRed = sT + SRED_OFF;

    const int t   = threadIdx.x;
    const int blk = blockIdx.x;
    const int pix = t >> 1;                  // 0..127
    const int g   = t & 1;                   // group 0/1
    const int P   = blk * TILE + pix;        // global pixel
    const int b   = P >> 12;                 // batch
    const int hw  = P & 4095;

    const float* zp  = z   + (size_t)(b * 18 + g * 9) * HW + hw;
    float*       zqp = out + OFF_ZQ + (size_t)(b * 18 + g * 9) * HW + hw;

    // ---- Phase 1: per-(pixel,group) work ----
    // ent = ln( prod_j (1+E_j) ) + sum_j q_j*a_j,  E=e^{-4|v|}, q=E/(1+E)
    float p[9];
    unsigned gidx = 0;
    float commit = 0.f, qa = 0.f, prodE = 1.f;
#pragma unroll
    for (int j = 0; j < 9; j++) {
        float v = zp[j * HW];
        bool s = v > 0.f;
        gidx = (gidx << 1) | (unsigned)s;
        float zh = s ? 1.f : -1.f;
        zqp[j * HW] = zh;                    // zq forward value == sign(z)
        float d = zh - v;
        commit += d * d;
        float a = 4.f * fabsf(v);
        float E = __expf(-a);
        float onepE = 1.f + E;
        float r = __fdividef(1.f, onepE);
        float q = E * r;
        p[j] = s ? r : q;                    // sigmoid(4v)
        qa += q * a;
        prodE *= onepE;
    }
    float ent = __logf(prodE) + qa;

    // indices: pair of threads (g=0,g=1) are adjacent lanes
    unsigned other = __shfl_xor_sync(0xffffffffu, gidx, 1);
    out[OFF_GIDX + (size_t)P * 2 + g] = (float)gidx;
    if (g == 0)
        out[OFF_IDX + P] = (float)(gidx * 512u + other);

    // build hi[16]/lo[32] in regs, write transposed (conflict-free STS)
    const int col = g * GOFF + pix;
    {
        float hi[16];
        hi[0] = 1.f - p[0]; hi[1] = p[0];
#pragma unroll
        for (int c = 1; c < 4; c++) {
            const int n = 1 << c;
#pragma unroll
            for (int i = n - 1; i >= 0; i--) {
                float v = hi[i];
                hi[2 * i + 1] = v * p[c];
                hi[2 * i]     = v * (1.f - p[c]);
            }
        }
#pragma unroll
        for (int i = 0; i < 16; i++) sT[i * RS + col] = hi[i];
    }
    {
        float lo[32];
        lo[0] = 1.f - p[4]; lo[1] = p[4];
#pragma unroll
        for (int c = 1; c < 5; c++) {
            const int n = 1 << c;
#pragma unroll
            for (int i = n - 1; i >= 0; i--) {
                float v = lo[i];
                lo[2 * i + 1] = v * p[4 + c];
                lo[2 * i]     = v * (1.f - p[4 + c]);
            }
        }
#pragma unroll
        for (int i = 0; i < 32; i++) sT[(16 + i) * RS + col] = lo[i];
    }

    // block-reduce commit & entropy (deterministic shuffle tree)
#pragma unroll
    for (int o = 16; o; o >>= 1) {
        commit += __shfl_down_sync(0xffffffffu, commit, o);
        ent    += __shfl_down_sync(0xffffffffu, ent, o);
    }
    const int wid = t >> 5, lid = t & 31;
    if (lid == 0) { sRed[wid] = commit; sRed[8 + wid] = ent; }

    __syncthreads();   // tables + sRed ready

    if (t == 0) {
        float c = 0.f, e = 0.f;
#pragma unroll
        for (int w = 0; w < 8; w++) { c += sRed[w]; e += sRed[8 + w]; }
        g_pcommit[blk] = c;
        g_pent[blk]    = e;
    }

    // ---- Phase 2: AVG[g][i][j] = sum_px hi[g][px][i]*lo[g][px][j]
    // Warp = (group, hi-quarter). Lane (ti,tj) -> hi row 4q+ti, lo rows 16+tj+8m.
    // hi load: 4 unique rows at 4 distinct bank-quads + tj-broadcast = 1 wavefront.
    // lo load: 8 unique rows at 8 distinct bank-quads = 1 wavefront.
    {
        const int w2   = t >> 5;             // 0..7
        const int gg   = w2 >> 2;            // group
        const int q    = w2 & 3;             // hi quarter
        const int ti   = lid >> 3;           // 0..3
        const int tj   = lid & 7;            // 0..7
        const float* pH = sT + (4 * q + ti) * RS + gg * GOFF;
        const float* pL = sT + (16 + tj)    * RS + gg * GOFF;

        unsigned long long a0 = 0ull, a1 = 0ull, a2 = 0ull, a3 = 0ull;
#pragma unroll 2
        for (int px = 0; px < TILE; px += 4) {
            ulonglong2 h  = *(const ulonglong2*)(pH + px);
            ulonglong2 l0 = *(const ulonglong2*)(pL + px);
            ulonglong2 l1 = *(const ulonglong2*)(pL +  8 * RS + px);
            ulonglong2 l2 = *(const ulonglong2*)(pL + 16 * RS + px);
            ulonglong2 l3 = *(const ulonglong2*)(pL + 24 * RS + px);
            fma2(a0, h.x, l0.x); fma2(a0, h.y, l0.y);
            fma2(a1, h.x, l1.x); fma2(a1, h.y, l1.y);
            fma2(a2, h.x, l2.x); fma2(a2, h.y, l2.y);
            fma2(a3, h.x, l3.x); fma2(a3, h.y, l3.y);
        }

        float* gp = g_pavg + (size_t)blk * 1024 + gg * 512 + (4 * q + ti) * 32 + tj;
        gp[0]  = hsum2(a0);
        gp[8]  = hsum2(a1);
        gp[16] = hsum2(a2);
        gp[24] = hsum2(a3);
    }
}

// 512 block-partials -> NSPLIT partials, parallel across 32 blocks
__global__ void __launch_bounds__(256) bsq_reduce() {
    const int slot  = blockIdx.y * 256 + threadIdx.x;
    const int bbase = blockIdx.x * (NBLK / NSPLIT);
    float s = 0.f;
#pragma unroll 8
    for (int j = 0; j < NBLK / NSPLIT; j++)
        s += g_pavg[(size_t)(bbase + j) * 1024 + slot];
    g_red[blockIdx.x * 1024 + slot] = s;
}

__global__ void __launch_bounds__(1024) bsq_final(float* __restrict__ out) {
    __shared__ float sr[64];
    const int t = threadIdx.x;            // one per (g,d) slot
    const int wid = t >> 5, lid = t & 31;

    float s = 0.f;
#pragma unroll
    for (int sp = 0; sp < NSPLIT; sp++) s += g_red[sp * 1024 + t];
    float avg = s * (1.f / (float)NPIX);
    out[OFF_AVGP + t] = avg;

    float cterm = -avg * __logf(avg + 1e-8f);
#pragma unroll
    for (int o = 16; o; o >>= 1) cterm += __shfl_down_sync(0xffffffffu, cterm, o);
    if (lid == 0) sr[wid] = cterm;        // warps 0..31

    // commit / entropy partials: threads 0..511
    float cm = (t < NBLK) ? g_pcommit[t] : 0.f;
    float en = (t < NBLK) ? g_pent[t]    : 0.f;
#pragma unroll
    for (int o = 16; o; o >>= 1) {
        cm += __shfl_down_sync(0xffffffffu, cm, o);
        en += __shfl_down_sync(0xffffffffu, en, o);
    }
    __syncthreads();
    if (lid == 0 && wid < 16) { sr[32 + wid] = cm; sr[48 + wid] = en; }
    __syncthreads();

    if (t == 0) {
        float cbE = 0.f, cmS = 0.f, enS = 0.f;
#pragma unroll
        for (int w = 0; w < 32; w++) cbE += sr[w];
#pragma unroll
        for (int w = 0; w < 16; w++) { cmS += sr[32 + w]; enS += sr[48 + w]; }
        float commit_loss = 0.25f * cmS * (1.f / (float)NPIX);
        float pse = enS * (1.f / (float)NPIX);
        float loss = commit_loss + pse - cbE;    // GAMMA0=GAMMA=ZETA=INV_T=1
        out[OFF_LOSS] = loss;
        out[OFF_CBE]  = cbE;
    }
}

extern "C" void kernel_launch(void* const* d_in, const int* in_sizes, int n_in,
                              void* d_out, int out_size) {
    const float* z = (const float*)d_in[0];
    float* out = (float*)d_out;

    const size_t smem = SMEM_FLOATS * sizeof(float);   // 56,320 B
    cudaFuncSetAttribute(bsq_main, cudaFuncAttributeMaxDynamicSharedMemorySize, 64 * 1024);

    bsq_main<<<NBLK, NTHR, smem>>>(z, out);
    bsq_reduce<<<dim3(NSPLIT, 4), 256>>>();
    bsq_final<<<1, 1024>>>(out);
}

// round 7
// speedup vs baseline: 1.2208x; 1.2208x over previous
#include <cuda_runtime.h>
#include <math.h>

// Problem constants
#define NPIX   65536        // B*H*W = 16*64*64
#define HW     4096         // 64*64
#define TILE   128          // pixels per block
#define NBLK   (NPIX/TILE)  // 512
#define NTHR   256
#define NSPLIT 8            // reduction splits (512 blocks -> 8 partials)

// Transposed table layout: sT[row*RS + g*GOFF + pix]
//   rows 0..15  = hi[i],  rows 16..47 = lo[j]
//   RS = 292: 292 mod 32 = 4 -> bank(row) = 4*row mod 32 (lo rows 16+tc+8k spread fully)
//   GOFF = 144 (mod 32 == 16 -> phase-1 STS conflict-free)
#define RS    292
#define GOFF  144
#define SRED_OFF (48 * RS)       // 14016
#define SMEM_FLOATS (SRED_OFF + 64)

// Output layout (flattened tuple, float32):
// zq[16,18,64,64] | loss | cb_entropy | indices[16,64,64] | group_indices[16,64,64,2] | avg_prob[2,512]
#define OFF_ZQ    0
#define OFF_LOSS  1179648
#define OFF_CBE   1179649
#define OFF_IDX   1179650
#define OFF_GIDX  1245186
#define OFF_AVGP  1376258

// Deterministic per-block partials (no float atomics -> bitwise reproducible)
__device__ float g_pavg[NBLK * 1024];
__device__ float g_red[NSPLIT * 1024];
__device__ float g_pcommit[NBLK];
__device__ float g_pent[NBLK];

__device__ __forceinline__ void fma2(unsigned long long& acc,
                                     unsigned long long a, unsigned long long b) {
    asm("fma.rn.f32x2 %0, %1, %2, %0;" : "+l"(acc) : "l"(a), "l"(b));
}
__device__ __forceinline__ float hsum2(unsigned long long acc) {
    float lo, hi;
    asm("mov.b64 {%0, %1}, %2;" : "=f"(lo), "=f"(hi) : "l"(acc));
    return lo + hi;
}

__global__ void __launch_bounds__(NTHR) bsq_main(const float* __restrict__ z,
                                                 float* __restrict__ out) {
    extern __shared__ float sT[];
    float* sRed = sT + SRED_OFF;

    const int t   = threadIdx.x;
    const int blk = blockIdx.x;
    const int pix = t >> 1;                  // 0..127
    const int g   = t & 1;                   // group 0/1
    const int P   = blk * TILE + pix;        // global pixel
    const int b   = P >> 12;                 // batch
    const int hw  = P & 4095;

    const float* zp  = z   + (size_t)(b * 18 + g * 9) * HW + hw;
    float*       zqp = out + OFF_ZQ + (size_t)(b * 18 + g * 9) * HW + hw;

    // ---- Phase 1: per-(pixel,group) work ----
    // ent = ln( prod_j (1+E_j) ) + sum_j q_j*a_j,  E=e^{-4|v|}, q=E/(1+E)
    float p[9];
    unsigned gidx = 0;
    float commit = 0.f, qa = 0.f, prodE = 1.f;
#pragma unroll
    for (int j = 0; j < 9; j++) {
        float v = zp[j * HW];
        bool s = v > 0.f;
        gidx = (gidx << 1) | (unsigned)s;
        float zh = s ? 1.f : -1.f;
        zqp[j * HW] = zh;                    // zq forward value == sign(z)
        float d = zh - v;
        commit += d * d;
        float a = 4.f * fabsf(v);
        float E = __expf(-a);
        float onepE = 1.f + E;
        float r = __fdividef(1.f, onepE);
        float q = E * r;
        p[j] = s ? r : q;                    // sigmoid(4v)
        qa += q * a;
        prodE *= onepE;
    }
    float ent = __logf(prodE) + qa;

    // indices: pair of threads (g=0,g=1) are adjacent lanes
    unsigned other = __shfl_xor_sync(0xffffffffu, gidx, 1);
    out[OFF_GIDX + (size_t)P * 2 + g] = (float)gidx;
    if (g == 0)
        out[OFF_IDX + P] = (float)(gidx * 512u + other);

    // build hi[16]/lo[32] in regs, write transposed (conflict-free STS)
    const int col = g * GOFF + pix;
    {
        float hi[16];
        hi[0] = 1.f - p[0]; hi[1] = p[0];
#pragma unroll
        for (int c = 1; c < 4; c++) {
            const int n = 1 << c;
#pragma unroll
            for (int i = n - 1; i >= 0; i--) {
                float v = hi[i];
                hi[2 * i + 1] = v * p[c];
                hi[2 * i]     = v * (1.f - p[c]);
            }
        }
#pragma unroll
        for (int i = 0; i < 16; i++) sT[i * RS + col] = hi[i];
    }
    {
        float lo[32];
        lo[0] = 1.f - p[4]; lo[1] = p[4];
#pragma unroll
        for (int c = 1; c < 5; c++) {
            const int n = 1 << c;
#pragma unroll
            for (int i = n - 1; i >= 0; i--) {
                float v = lo[i];
                lo[2 * i + 1] = v * p[4 + c];
                lo[2 * i]     = v * (1.f - p[4 + c]);
            }
        }
#pragma unroll
        for (int i = 0; i < 32; i++) sT[(16 + i) * RS + col] = lo[i];
    }

    // block-reduce commit & entropy (deterministic shuffle tree)
#pragma unroll
    for (int o = 16; o; o >>= 1) {
        commit += __shfl_down_sync(0xffffffffu, commit, o);
        ent    += __shfl_down_sync(0xffffffffu, ent, o);
    }
    const int wid = t >> 5, lid = t & 31;
    if (lid == 0) { sRed[wid] = commit; sRed[8 + wid] = ent; }

    __syncthreads();   // tables + sRed ready

    if (t == 0) {
        float c = 0.f, e = 0.f;
#pragma unroll
        for (int w = 0; w < 8; w++) { c += sRed[w]; e += sRed[8 + w]; }
        g_pcommit[blk] = c;
        g_pent[blk]    = e;
    }

    // ---- Phase 2: AVG[g][i][j] = sum_px hi[g][px][i]*lo[g][px][j]
    // 4x4 register tile: thread (s,gg,tr,tc) owns i in {tr+4k}, j in {tc+8k},
    // sweeping px subset s (32 px). 8 LDS.128 -> 32 fma2 per 4-px chunk.
    const int s2  = t >> 6;                // px subset 0..3
    const int u   = t & 63;
    const int gg  = u >> 5;                // == warp parity
    const int tr  = (u >> 3) & 3;          // == lid>>3 (quarter-warp uniform)
    const int tc  = u & 7;                 // == lid&7
    {
        const float* pH = sT + tr        * RS + gg * GOFF;   // hi rows tr+4k
        const float* pL = sT + (16 + tc) * RS + gg * GOFF;   // lo rows 16+tc+8k

        unsigned long long acc[4][4];
#pragma unroll
        for (int k1 = 0; k1 < 4; k1++)
#pragma unroll
            for (int k2 = 0; k2 < 4; k2++) acc[k1][k2] = 0ull;

        const int px0 = s2 * 32;
#pragma unroll 2
        for (int px = px0; px < px0 + 32; px += 4) {
            ulonglong2 h[4], l[4];
#pragma unroll
            for (int k = 0; k < 4; k++) h[k] = *(const ulonglong2*)(pH + (4 * k) * RS + px);
#pragma unroll
            for (int k = 0; k < 4; k++) l[k] = *(const ulonglong2*)(pL + (8 * k) * RS + px);
#pragma unroll
            for (int k1 = 0; k1 < 4; k1++)
#pragma unroll
                for (int k2 = 0; k2 < 4; k2++) {
                    fma2(acc[k1][k2], h[k1].x, l[k2].x);
                    fma2(acc[k1][k2], h[k1].y, l[k2].y);
                }
        }

        __syncthreads();   // all table reads done; safe to overwrite sT

        // stash: skewed stride-20 layout, conflict-free STS.128
        float* st = sT + t * 20;
#pragma unroll
        for (int k1 = 0; k1 < 4; k1++) {
            float4 v = make_float4(hsum2(acc[k1][0]), hsum2(acc[k1][1]),
                                   hsum2(acc[k1][2]), hsum2(acc[k1][3]));
            *(float4*)(st + k1 * 4) = v;
        }
    }
    __syncthreads();

    // combine 4 px-subsets; thread t owns slots 4t..4t+3
    {
        const int slot0 = 4 * t;
        const int ggr = slot0 >> 9;
        const int d   = slot0 & 511;
        const int i   = d >> 5;
        const int j0  = d & 31;              // multiple of 4
        const int k1  = i >> 2;
        const int trr = i & 3;
        const int k2  = j0 >> 3;
        const int e   = k1 * 4 + k2;
        float res[4];
#pragma unroll
        for (int m = 0; m < 4; m++) {
            const int tcc = (j0 & 7) + m;
            const int uw  = ggr * 32 + trr * 8 + tcc;
            float v = 0.f;
#pragma unroll
            for (int q = 0; q < 4; q++)
                v += sT[(q * 64 + uw) * 20 + e];
            res[m] = v;
        }
        *(float4*)(g_pavg + (size_t)blk * 1024 + slot0) =
            make_float4(res[0], res[1], res[2], res[3]);
    }
}

// 512 block-partials -> NSPLIT partials, parallel across 32 blocks
__global__ void __launch_bounds__(256) bsq_reduce() {
    const int slot  = blockIdx.y * 256 + threadIdx.x;
    const int bbase = blockIdx.x * (NBLK / NSPLIT);
    float s = 0.f;
#pragma unroll 8
    for (int j = 0; j < NBLK / NSPLIT; j++)
        s += g_pavg[(size_t)(bbase + j) * 1024 + slot];
    g_red[blockIdx.x * 1024 + slot] = s;
}

__global__ void __launch_bounds__(1024) bsq_final(float* __restrict__ out) {
    __shared__ float sr[64];
    const int t = threadIdx.x;            // one per (g,d) slot
    const int wid = t >> 5, lid = t & 31;

    float s = 0.f;
#pragma unroll
    for (int sp = 0; sp < NSPLIT; sp++) s += g_red[sp * 1024 + t];
    float avg = s * (1.f / (float)NPIX);
    out[OFF_AVGP + t] = avg;

    float cterm = -avg * __logf(avg + 1e-8f);
#pragma unroll
    for (int o = 16; o; o >>= 1) cterm += __shfl_down_sync(0xffffffffu, cterm, o);
    if (lid == 0) sr[wid] = cterm;        // warps 0..31

    // commit / entropy partials: threads 0..511
    float cm = (t < NBLK) ? g_pcommit[t] : 0.f;
    float en = (t < NBLK) ? g_pent[t]    : 0.f;
#pragma unroll
    for (int o = 16; o; o >>= 1) {
        cm += __shfl_down_sync(0xffffffffu, cm, o);
        en += __shfl_down_sync(0xffffffffu, en, o);
    }
    __syncthreads();
    if (lid == 0 && wid < 16) { sr[32 + wid] = cm; sr[48 + wid] = en; }
    __syncthreads();

    if (t == 0) {
        float cbE = 0.f, cmS = 0.f, enS = 0.f;
#pragma unroll
        for (int w = 0; w < 32; w++) cbE += sr[w];
#pragma unroll
        for (int w = 0; w < 16; w++) { cmS += sr[32 + w]; enS += sr[48 + w]; }
        float commit_loss = 0.25f * cmS * (1.f / (float)NPIX);
        float pse = enS * (1.f / (float)NPIX);
        float loss = commit_loss + pse - cbE;    // GAMMA0=GAMMA=ZETA=INV_T=1
        out[OFF_LOSS] = loss;
        out[OFF_CBE]  = cbE;
    }
}

extern "C" void kernel_launch(void* const* d_in, const int* in_sizes, int n_in,
                              void* d_out, int out_size) {
    const float* z = (const float*)d_in[0];
    float* out = (float*)d_out;

    const size_t smem = SMEM_FLOATS * sizeof(float);   // 56,320 B
    cudaFuncSetAttribute(bsq_main, cudaFuncAttributeMaxDynamicSharedMemorySize, 64 * 1024);

    bsq_main<<<NBLK, NTHR, smem>>>(z, out);
    bsq_reduce<<<dim3(NSPLIT, 4), 256>>>();
    bsq_final<<<1, 1024>>>(out);
}

// round 8
// speedup vs baseline: 1.4250x; 1.1673x over previous
#include <cuda_runtime.h>
#include <math.h>

// Problem constants
#define NPIX   65536        // B*H*W = 16*64*64
#define HW     4096         // 64*64
#define TILE   128          // pixels per block
#define NBLK   (NPIX/TILE)  // 512
#define NTHR   256
#define NSPLIT 32           // tail splits (512 main-blocks -> 32 partials)

// Transposed table layout: sT[row*RS + g*GOFF + pix]
#define RS    292
#define GOFF  144
#define SRED_OFF (48 * RS)       // 14016
#define SMEM_FLOATS (SRED_OFF + 64)

// Output layout (flattened tuple, float32):
// zq[16,18,64,64] | loss | cb_entropy | indices[16,64,64] | group_indices[16,64,64,2] | avg_prob[2,512]
#define OFF_ZQ    0
#define OFF_LOSS  1179648
#define OFF_CBE   1179649
#define OFF_IDX   1179650
#define OFF_GIDX  1245186
#define OFF_AVGP  1376258

// Deterministic per-block partials (no float atomics -> bitwise reproducible)
__device__ float g_pavg[NBLK * 1024];
__device__ float g_red[NSPLIT * 1024];
__device__ float g_pcommit[NBLK];
__device__ float g_pent[NBLK];
__device__ int   g_cnt;          // zero-init; self-resetting each launch

__device__ __forceinline__ void fma2(unsigned long long& acc,
                                     unsigned long long a, unsigned long long b) {
    asm("fma.rn.f32x2 %0, %1, %2, %0;" : "+l"(acc) : "l"(a), "l"(b));
}
__device__ __forceinline__ float hsum2(unsigned long long acc) {
    float lo, hi;
    asm("mov.b64 {%0, %1}, %2;" : "=f"(lo), "=f"(hi) : "l"(acc));
    return lo + hi;
}

__global__ void __launch_bounds__(NTHR) bsq_main(const float* __restrict__ z,
                                                 float* __restrict__ out) {
    extern __shared__ float sT[];
    float* sRed = sT + SRED_OFF;

    const int t   = threadIdx.x;
    const int blk = blockIdx.x;
    const int pix = t >> 1;                  // 0..127
    const int g   = t & 1;                   // group 0/1
    const int P   = blk * TILE + pix;        // global pixel
    const int b   = P >> 12;                 // batch
    const int hw  = P & 4095;

    const float* zp  = z   + (size_t)(b * 18 + g * 9) * HW + hw;
    float*       zqp = out + OFF_ZQ + (size_t)(b * 18 + g * 9) * HW + hw;

    // ---- Phase 1: per-(pixel,group) work ----
    // ent = ln( prod_j (1+E_j) ) + sum_j q_j*a_j,  E=e^{-4|v|}, q=E/(1+E)
    float p[9];
    unsigned gidx = 0;
    float commit = 0.f, qa = 0.f, prodE = 1.f;
#pragma unroll
    for (int j = 0; j < 9; j++) {
        float v = zp[j * HW];
        bool s = v > 0.f;
        gidx = (gidx << 1) | (unsigned)s;
        float zh = s ? 1.f : -1.f;
        zqp[j * HW] = zh;                    // zq forward value == sign(z)
        float d = zh - v;
        commit += d * d;
        float a = 4.f * fabsf(v);
        float E = __expf(-a);
        float onepE = 1.f + E;
        float r = __fdividef(1.f, onepE);
        float q = E * r;
        p[j] = s ? r : q;                    // sigmoid(4v)
        qa += q * a;
        prodE *= onepE;
    }
    float ent = __logf(prodE) + qa;

    // indices: pair of threads (g=0,g=1) are adjacent lanes
    unsigned other = __shfl_xor_sync(0xffffffffu, gidx, 1);
    out[OFF_GIDX + (size_t)P * 2 + g] = (float)gidx;
    if (g == 0)
        out[OFF_IDX + P] = (float)(gidx * 512u + other);

    // build hi[16]/lo[32] in regs, write transposed (conflict-free STS)
    const int col = g * GOFF + pix;
    {
        float hi[16];
        hi[0] = 1.f - p[0]; hi[1] = p[0];
#pragma unroll
        for (int c = 1; c < 4; c++) {
            const int n = 1 << c;
#pragma unroll
            for (int i = n - 1; i >= 0; i--) {
                float v = hi[i];
                hi[2 * i + 1] = v * p[c];
                hi[2 * i]     = v * (1.f - p[c]);
            }
        }
#pragma unroll
        for (int i = 0; i < 16; i++) sT[i * RS + col] = hi[i];
    }
    {
        float lo[32];
        lo[0] = 1.f - p[4]; lo[1] = p[4];
#pragma unroll
        for (int c = 1; c < 5; c++) {
            const int n = 1 << c;
#pragma unroll
            for (int i = n - 1; i >= 0; i--) {
                float v = lo[i];
                lo[2 * i + 1] = v * p[4 + c];
                lo[2 * i]     = v * (1.f - p[4 + c]);
            }
        }
#pragma unroll
        for (int i = 0; i < 32; i++) sT[(16 + i) * RS + col] = lo[i];
    }

    // block-reduce commit & entropy (deterministic shuffle tree)
#pragma unroll
    for (int o = 16; o; o >>= 1) {
        commit += __shfl_down_sync(0xffffffffu, commit, o);
        ent    += __shfl_down_sync(0xffffffffu, ent, o);
    }
    const int wid = t >> 5, lid = t & 31;
    if (lid == 0) { sRed[wid] = commit; sRed[8 + wid] = ent; }

    __syncthreads();   // tables + sRed ready

    if (t == 0) {
        float c = 0.f, e = 0.f;
#pragma unroll
        for (int w = 0; w < 8; w++) { c += sRed[w]; e += sRed[8 + w]; }
        g_pcommit[blk] = c;
        g_pent[blk]    = e;
    }

    // ---- Phase 2: AVG[g][i][j] = sum_px hi[g][px][i]*lo[g][px][j]
    // 4x4 register tile: thread (s,gg,tr,tc) owns i in {tr+4k}, j in {tc+8k},
    // sweeping px subset s (32 px). 8 LDS.128 -> 32 fma2 per 4-px chunk.
    const int s2  = t >> 6;                // px subset 0..3
    const int u   = t & 63;
    const int gg  = u >> 5;                // == warp parity
    const int tr  = (u >> 3) & 3;          // quarter-warp uniform
    const int tc  = u & 7;
    {
        const float* pH = sT + tr        * RS + gg * GOFF;   // hi rows tr+4k
        const float* pL = sT + (16 + tc) * RS + gg * GOFF;   // lo rows 16+tc+8k

        unsigned long long acc[4][4];
#pragma unroll
        for (int k1 = 0; k1 < 4; k1++)
#pragma unroll
            for (int k2 = 0; k2 < 4; k2++) acc[k1][k2] = 0ull;

        const int px0 = s2 * 32;
#pragma unroll 2
        for (int px = px0; px < px0 + 32; px += 4) {
            ulonglong2 h[4], l[4];
#pragma unroll
            for (int k = 0; k < 4; k++) h[k] = *(const ulonglong2*)(pH + (4 * k) * RS + px);
#pragma unroll
            for (int k = 0; k < 4; k++) l[k] = *(const ulonglong2*)(pL + (8 * k) * RS + px);
#pragma unroll
            for (int k1 = 0; k1 < 4; k1++)
#pragma unroll
                for (int k2 = 0; k2 < 4; k2++) {
                    fma2(acc[k1][k2], h[k1].x, l[k2].x);
                    fma2(acc[k1][k2], h[k1].y, l[k2].y);
                }
        }

        __syncthreads();   // all table reads done; safe to overwrite sT

        // stash: skewed stride-20 layout, conflict-free STS.128
        float* st = sT + t * 20;
#pragma unroll
        for (int k1 = 0; k1 < 4; k1++) {
            float4 v = make_float4(hsum2(acc[k1][0]), hsum2(acc[k1][1]),
                                   hsum2(acc[k1][2]), hsum2(acc[k1][3]));
            *(float4*)(st + k1 * 4) = v;
        }
    }
    __syncthreads();

    // combine 4 px-subsets; thread t owns slots 4t..4t+3
    {
        const int slot0 = 4 * t;
        const int ggr = slot0 >> 9;
        const int d   = slot0 & 511;
        const int i   = d >> 5;
        const int j0  = d & 31;              // multiple of 4
        const int k1  = i >> 2;
        const int trr = i & 3;
        const int k2  = j0 >> 3;
        const int e   = k1 * 4 + k2;
        float res[4];
#pragma unroll
        for (int m = 0; m < 4; m++) {
            const int tcc = (j0 & 7) + m;
            const int uw  = ggr * 32 + trr * 8 + tcc;
            float v = 0.f;
#pragma unroll
            for (int q = 0; q < 4; q++)
                v += sT[(q * 64 + uw) * 20 + e];
            res[m] = v;
        }
        *(float4*)(g_pavg + (size_t)blk * 1024 + slot0) =
            make_float4(res[0], res[1], res[2], res[3]);
    }
}

// Fused tail: 32 blocks each reduce 16 main-block partials; the last-arriving
// block performs the finalization. Fixed summation order -> deterministic
// regardless of arrival order. Counter self-resets for graph replay.
__global__ void __launch_bounds__(1024) bsq_tail(float* __restrict__ out) {
    __shared__ float sr[64];
    __shared__ int sLast;
    const int t   = threadIdx.x;
    const int blk = blockIdx.x;
    const int wid = t >> 5, lid = t & 31;

    // split-sum: coalesced across t, MLP 16
    {
        float s = 0.f;
        const int bbase = blk * (NBLK / NSPLIT);
#pragma unroll
        for (int j = 0; j < NBLK / NSPLIT; j++)
            s += g_pavg[(size_t)(bbase + j) * 1024 + t];
        g_red[blk * 1024 + t] = s;
    }
    __threadfence();
    if (t == 0) {
        int v = atomicAdd(&g_cnt, 1);
        sLast = (v == NSPLIT - 1);
    }
    __syncthreads();
    if (!sLast) return;

    // ---- finalization (last block only) ----
    float s2 = 0.f;
#pragma unroll
    for (int sp = 0; sp < NSPLIT; sp++) s2 += g_red[sp * 1024 + t];
    float avg = s2 * (1.f / (float)NPIX);
    out[OFF_AVGP + t] = avg;

    float cterm = -avg * __logf(avg + 1e-8f);
#pragma unroll
    for (int o = 16; o; o >>= 1) cterm += __shfl_down_sync(0xffffffffu, cterm, o);
    if (lid == 0) sr[wid] = cterm;        // warps 0..31

    // commit / entropy partials: threads 0..511
    float cm = (t < NBLK) ? g_pcommit[t] : 0.f;
    float en = (t < NBLK) ? g_pent[t]    : 0.f;
#pragma unroll
    for (int o = 16; o; o >>= 1) {
        cm += __shfl_down_sync(0xffffffffu, cm, o);
        en += __shfl_down_sync(0xffffffffu, en, o);
    }
    __syncthreads();
    if (lid == 0 && wid < 16) { sr[32 + wid] = cm; sr[48 + wid] = en; }
    __syncthreads();

    if (t == 0) {
        float cbE = 0.f, cmS = 0.f, enS = 0.f;
#pragma unroll
        for (int w = 0; w < 32; w++) cbE += sr[w];
#pragma unroll
        for (int w = 0; w < 16; w++) { cmS += sr[32 + w]; enS += sr[48 + w]; }
        float commit_loss = 0.25f * cmS * (1.f / (float)NPIX);
        float pse = enS * (1.f / (float)NPIX);
        float loss = commit_loss + pse - cbE;    // GAMMA0=GAMMA=ZETA=INV_T=1
        out[OFF_LOSS] = loss;
        out[OFF_CBE]  = cbE;
        g_cnt = 0;                                // reset for next graph replay
    }
}

extern "C" void kernel_launch(void* const* d_in, const int* in_sizes, int n_in,
                              void* d_out, int out_size) {
    const float* z = (const float*)d_in[0];
    float* out = (float*)d_out;

    const size_t smem = SMEM_FLOATS * sizeof(float);   // 56,320 B
    cudaFuncSetAttribute(bsq_main, cudaFuncAttributeMaxDynamicSharedMemorySize, 64 * 1024);

    bsq_main<<<NBLK, NTHR, smem>>>(z, out);
    bsq_tail<<<NSPLIT, 1024>>>(out);
}